// round 4
// baseline (speedup 1.0000x reference)
#include <cuda_runtime.h>

#define N_NODES 100000
#define N_EDGES 3200000
#define R0 16
#define R1 8
#define R2 16
#define N1 32
#define CAP 96   // max in-degree slots; Binomial(3.2M,1e-5) max ~60, 96 is >>safe

// ---------------- scratch (device globals; no allocation allowed) ----------------
__device__ __align__(16) float g_y1[N_NODES * R1];   // x @ W_rel1
__device__ __align__(16) float g_r1[N_NODES * R1];   // x @ W_root1 + b_rel1
__device__ __align__(16) float g_h1[N_NODES * R1];   // layer-1 output
__device__ int g_count[N_NODES];                     // in-degree (built per call)
__device__ int g_csr[N_NODES * CAP];                 // incoming src ids, 38.4MB
__device__ double g_sum;

// ---------------- K1: per-node pre-transform + zero counters ----------------
__global__ void k_node1(const float* __restrict__ x,
                        const float* __restrict__ Wrel,
                        const float* __restrict__ brel,
                        const float* __restrict__ Wroot) {
    __shared__ float sWr[R0 * R1];
    __shared__ float sWo[R0 * R1];
    __shared__ float sb[R1];
    int t = threadIdx.x;
    if (t < R0 * R1) { sWr[t] = Wrel[t]; sWo[t] = Wroot[t]; }
    if (t < R1) sb[t] = brel[t];
    __syncthreads();

    int i = blockIdx.x * blockDim.x + t;
    if (i == 0) g_sum = 0.0;
    if (i >= N_NODES) return;

    g_count[i] = 0;

    float xr[R0];
    const float4* xp = reinterpret_cast<const float4*>(x + (size_t)i * R0);
#pragma unroll
    for (int q = 0; q < R0 / 4; q++) {
        float4 v = xp[q];
        xr[4 * q + 0] = v.x; xr[4 * q + 1] = v.y;
        xr[4 * q + 2] = v.z; xr[4 * q + 3] = v.w;
    }

    float y[R1], r[R1];
#pragma unroll
    for (int k = 0; k < R1; k++) { y[k] = 0.f; r[k] = sb[k]; }
#pragma unroll
    for (int j = 0; j < R0; j++) {
        float xj = xr[j];
#pragma unroll
        for (int k = 0; k < R1; k++) {
            y[k] += xj * sWr[j * R1 + k];
            r[k] += xj * sWo[j * R1 + k];
        }
    }

    float4* yp = reinterpret_cast<float4*>(g_y1 + (size_t)i * R1);
    float4* rp = reinterpret_cast<float4*>(g_r1 + (size_t)i * R1);
    yp[0] = make_float4(y[0], y[1], y[2], y[3]);
    yp[1] = make_float4(y[4], y[5], y[6], y[7]);
    rp[0] = make_float4(r[0], r[1], r[2], r[3]);
    rp[1] = make_float4(r[4], r[5], r[6], r[7]);
}

// ---------------- K2: build fixed-capacity incoming CSR ----------------
__global__ __launch_bounds__(256)
void k_scatter(const int* __restrict__ ei) {
    int base = (blockIdx.x * blockDim.x + threadIdx.x) * 4;
    if (base >= N_EDGES) return;
    int4 s = __ldg(reinterpret_cast<const int4*>(ei + base));
    int4 d = __ldg(reinterpret_cast<const int4*>(ei + N_EDGES + base));

    int p0 = atomicAdd(&g_count[d.x], 1);
    int p1 = atomicAdd(&g_count[d.y], 1);
    int p2 = atomicAdd(&g_count[d.z], 1);
    int p3 = atomicAdd(&g_count[d.w], 1);
    if (p0 < CAP) g_csr[d.x * CAP + p0] = s.x;
    if (p1 < CAP) g_csr[d.y * CAP + p1] = s.y;
    if (p2 < CAP) g_csr[d.z * CAP + p2] = s.z;
    if (p3 < CAP) g_csr[d.w * CAP + p3] = s.w;
}

// ---------------- K3: pull aggregate layer 1 + relu ----------------
// warp per node: h1[i] = relu( sum_{j->i} y1[j] + r1[i] )
__global__ __launch_bounds__(256)
void k_pull1() {
    int node = (blockIdx.x * blockDim.x + threadIdx.x) >> 5;
    int lane = threadIdx.x & 31;
    if (node >= N_NODES) return;

    int deg = min(g_count[node], CAP);
    float a[R1];
#pragma unroll
    for (int k = 0; k < R1; k++) a[k] = 0.f;

    for (int e = lane; e < deg; e += 32) {
        int s = g_csr[node * CAP + e];
        const float4* p = reinterpret_cast<const float4*>(g_y1 + (size_t)s * R1);
        float4 u = __ldg(p), v = __ldg(p + 1);
        a[0] += u.x; a[1] += u.y; a[2] += u.z; a[3] += u.w;
        a[4] += v.x; a[5] += v.y; a[6] += v.z; a[7] += v.w;
    }
#pragma unroll
    for (int off = 16; off > 0; off >>= 1) {
#pragma unroll
        for (int k = 0; k < R1; k++)
            a[k] += __shfl_xor_sync(0xffffffffu, a[k], off);
    }

    if (lane == 0) {
        const float4* rp = reinterpret_cast<const float4*>(g_r1 + (size_t)node * R1);
        float4 r0 = rp[0], r1v = rp[1];
        float4 h0, h1v;
        h0.x = fmaxf(a[0] + r0.x, 0.f);  h0.y = fmaxf(a[1] + r0.y, 0.f);
        h0.z = fmaxf(a[2] + r0.z, 0.f);  h0.w = fmaxf(a[3] + r0.w, 0.f);
        h1v.x = fmaxf(a[4] + r1v.x, 0.f); h1v.y = fmaxf(a[5] + r1v.y, 0.f);
        h1v.z = fmaxf(a[6] + r1v.z, 0.f); h1v.w = fmaxf(a[7] + r1v.w, 0.f);
        float4* hp = reinterpret_cast<float4*>(g_h1 + (size_t)node * R1);
        hp[0] = h0; hp[1] = h1v;
    }
}

// ---------------- K4: pull aggregate layer 2 fused with conv2+fc1+fc2+sum ----------------
// warp per node; block-level partial sum -> one double atomic per block
__global__ __launch_bounds__(256)
void k_pull2(const float* __restrict__ Wrel2,
             const float* __restrict__ brel2,
             const float* __restrict__ Wroot2,
             const float* __restrict__ Wfc1,
             const float* __restrict__ bfc1,
             const float* __restrict__ Wfc2,
             const float* __restrict__ bfc2,
             float* __restrict__ out) {
    __shared__ float sWr[R1 * R2];   // 128
    __shared__ float sWo[R1 * R2];   // 128
    __shared__ float sb2[R2];        // 16
    __shared__ float sF1[R2 * N1];   // 512
    __shared__ float sb3[N1];        // 32
    __shared__ float sF2[N1];        // 32
    __shared__ float sbf2;
    __shared__ float swsum[8];       // per-warp node outputs

    int t = threadIdx.x;
    for (int j = t; j < R1 * R2; j += blockDim.x) { sWr[j] = Wrel2[j]; sWo[j] = Wroot2[j]; }
    for (int j = t; j < R2 * N1; j += blockDim.x) sF1[j] = Wfc1[j];
    if (t < R2) sb2[t] = brel2[t];
    if (t < N1) { sb3[t] = bfc1[t]; sF2[t] = Wfc2[t]; }
    if (t == 0) sbf2 = bfc2[0];
    __syncthreads();

    int node = (blockIdx.x * blockDim.x + t) >> 5;
    int lane = t & 31;
    int wid = t >> 5;

    float o = 0.f;
    if (node < N_NODES) {
        int deg = min(g_count[node], CAP);
        float a[R1];
#pragma unroll
        for (int k = 0; k < R1; k++) a[k] = 0.f;
        for (int e = lane; e < deg; e += 32) {
            int s = g_csr[node * CAP + e];
            const float4* p = reinterpret_cast<const float4*>(g_h1 + (size_t)s * R1);
            float4 u = __ldg(p), v = __ldg(p + 1);
            a[0] += u.x; a[1] += u.y; a[2] += u.z; a[3] += u.w;
            a[4] += v.x; a[5] += v.y; a[6] += v.z; a[7] += v.w;
        }
#pragma unroll
        for (int off = 16; off > 0; off >>= 1) {
#pragma unroll
            for (int k = 0; k < R1; k++)
                a[k] += __shfl_xor_sync(0xffffffffu, a[k], off);
        }

        // all lanes: own h1 row (broadcast sector)
        const float4* hp = reinterpret_cast<const float4*>(g_h1 + (size_t)node * R1);
        float4 u = __ldg(hp), v = __ldg(hp + 1);
        float hr[R1] = {u.x, u.y, u.z, u.w, v.x, v.y, v.z, v.w};

        // h2[k]: lane k (mod 16) computes feature k of conv2 output
        int k16 = lane & 15;
        float h2 = sb2[k16];
#pragma unroll
        for (int j = 0; j < R1; j++)
            h2 += a[j] * sWr[j * R2 + k16] + hr[j] * sWo[j * R2 + k16];
        h2 = fmaxf(h2, 0.f);

        // fc1: lane m computes output m (needs all 16 h2 via shfl broadcast)
        float uacc = sb3[lane];
#pragma unroll
        for (int k = 0; k < R2; k++) {
            float h2k = __shfl_sync(0xffffffffu, h2, k);
            uacc += h2k * sF1[k * N1 + lane];
        }
        float prod = fmaxf(uacc, 0.f) * sF2[lane];
#pragma unroll
        for (int off = 16; off > 0; off >>= 1)
            prod += __shfl_xor_sync(0xffffffffu, prod, off);
        if (lane == 0) {
            o = prod + sbf2;
            out[node] = o;
        }
    }

    // block reduce of per-node outputs -> one atomic per block
    if (lane == 0) swsum[wid] = o;
    __syncthreads();
    if (t == 0) {
        float bs = 0.f;
#pragma unroll
        for (int w = 0; w < 8; w++) bs += swsum[w];
        atomicAdd(&g_sum, (double)bs);
    }
}

// ---------------- K5: subtract mean ----------------
__global__ void k_mean(float* __restrict__ out) {
    int i = blockIdx.x * blockDim.x + threadIdx.x;
    if (i >= N_NODES) return;
    float m = (float)(g_sum / (double)N_NODES);
    out[i] -= m;
}

// ---------------- launch ----------------
extern "C" void kernel_launch(void* const* d_in, const int* in_sizes, int n_in,
                              void* d_out, int out_size) {
    const float* x      = (const float*)d_in[0];
    const int*   ei     = (const int*)d_in[1];
    const float* Wrel1  = (const float*)d_in[2];
    const float* brel1  = (const float*)d_in[3];
    const float* Wroot1 = (const float*)d_in[4];
    const float* Wrel2  = (const float*)d_in[5];
    const float* brel2  = (const float*)d_in[6];
    const float* Wroot2 = (const float*)d_in[7];
    const float* Wfc1   = (const float*)d_in[8];
    const float* bfc1   = (const float*)d_in[9];
    const float* Wfc2   = (const float*)d_in[10];
    const float* bfc2   = (const float*)d_in[11];
    float* out = (float*)d_out;

    const int scatter_blocks = N_EDGES / 4 / 256;          // 3125
    const int pull_blocks = (N_NODES * 32 + 255) / 256;    // 12500

    k_node1<<<(N_NODES + 127) / 128, 128>>>(x, Wrel1, brel1, Wroot1);
    k_scatter<<<scatter_blocks, 256>>>(ei);
    k_pull1<<<pull_blocks, 256>>>();
    k_pull2<<<pull_blocks, 256>>>(Wrel2, brel2, Wroot2, Wfc1, bfc1, Wfc2, bfc2, out);
    k_mean<<<(N_NODES + 255) / 256, 256>>>(out);
}

// round 5
// speedup vs baseline: 1.6083x; 1.6083x over previous
#include <cuda_runtime.h>
#include <cuda_fp16.h>

#define N_NODES 100000
#define N_EDGES 3200000
#define R0 16
#define R1 8
#define R2 16
#define N1 32
#define CAP 96   // max in-degree; Binomial(3.2M, 1e-5): mean 32, max ~60. 96 = 11 sigma.

// ---------------- scratch (device globals; no allocation allowed) ----------------
__device__ __align__(16) __half g_y1h[N_NODES * R1];  // x @ W_rel1, fp16 rows (gathered)
__device__ __align__(16) float  g_r1[N_NODES * R1];   // x @ W_root1 + b_rel1 (exact)
__device__ __align__(16) __half g_h1h[N_NODES * R1];  // layer-1 out, fp16 rows (gathered)
__device__ __align__(16) float  g_h1f[N_NODES * R1];  // layer-1 out, fp32 (root path)
__device__ int g_count[N_NODES];
__device__ int g_csr[CAP * N_NODES];                  // slot-major: csr[e*N + node]
__device__ double g_sum;

// pack 8 floats -> 8 halves (16B)
__device__ __forceinline__ uint4 pack_half8(const float* v) {
    __half2 h0 = __float22half2_rn(make_float2(v[0], v[1]));
    __half2 h1 = __float22half2_rn(make_float2(v[2], v[3]));
    __half2 h2 = __float22half2_rn(make_float2(v[4], v[5]));
    __half2 h3 = __float22half2_rn(make_float2(v[6], v[7]));
    uint4 u;
    u.x = *reinterpret_cast<unsigned*>(&h0);
    u.y = *reinterpret_cast<unsigned*>(&h1);
    u.z = *reinterpret_cast<unsigned*>(&h2);
    u.w = *reinterpret_cast<unsigned*>(&h3);
    return u;
}

// accumulate a packed half8 row into fp32 acc[8]
__device__ __forceinline__ void acc_half8(float* acc, uint4 u) {
    __half2 h0 = *reinterpret_cast<__half2*>(&u.x);
    __half2 h1 = *reinterpret_cast<__half2*>(&u.y);
    __half2 h2 = *reinterpret_cast<__half2*>(&u.z);
    __half2 h3 = *reinterpret_cast<__half2*>(&u.w);
    float2 f0 = __half22float2(h0), f1 = __half22float2(h1);
    float2 f2 = __half22float2(h2), f3 = __half22float2(h3);
    acc[0] += f0.x; acc[1] += f0.y; acc[2] += f1.x; acc[3] += f1.y;
    acc[4] += f2.x; acc[5] += f2.y; acc[6] += f3.x; acc[7] += f3.y;
}

// ---------------- K1: per-node pre-transform + zero counters ----------------
__global__ __launch_bounds__(128)
void k_node1(const float* __restrict__ x,
             const float* __restrict__ Wrel,
             const float* __restrict__ brel,
             const float* __restrict__ Wroot) {
    __shared__ float sWr[R0 * R1];
    __shared__ float sWo[R0 * R1];
    __shared__ float sb[R1];
    int t = threadIdx.x;
    if (t < R0 * R1) { sWr[t] = Wrel[t]; sWo[t] = Wroot[t]; }
    if (t < R1) sb[t] = brel[t];
    __syncthreads();

    int i = blockIdx.x * blockDim.x + t;
    if (i == 0) g_sum = 0.0;
    if (i >= N_NODES) return;

    g_count[i] = 0;

    float xr[R0];
    const float4* xp = reinterpret_cast<const float4*>(x + (size_t)i * R0);
#pragma unroll
    for (int q = 0; q < R0 / 4; q++) {
        float4 v = xp[q];
        xr[4 * q + 0] = v.x; xr[4 * q + 1] = v.y;
        xr[4 * q + 2] = v.z; xr[4 * q + 3] = v.w;
    }

    float y[R1], r[R1];
#pragma unroll
    for (int k = 0; k < R1; k++) { y[k] = 0.f; r[k] = sb[k]; }
#pragma unroll
    for (int j = 0; j < R0; j++) {
        float xj = xr[j];
#pragma unroll
        for (int k = 0; k < R1; k++) {
            y[k] += xj * sWr[j * R1 + k];
            r[k] += xj * sWo[j * R1 + k];
        }
    }

    reinterpret_cast<uint4*>(g_y1h)[i] = pack_half8(y);
    float4* rp = reinterpret_cast<float4*>(g_r1 + (size_t)i * R1);
    rp[0] = make_float4(r[0], r[1], r[2], r[3]);
    rp[1] = make_float4(r[4], r[5], r[6], r[7]);
}

// ---------------- K2: build slot-major incoming CSR ----------------
__global__ __launch_bounds__(256)
void k_scatter(const int* __restrict__ ei) {
    int base = (blockIdx.x * blockDim.x + threadIdx.x) * 4;
    if (base >= N_EDGES) return;
    int4 s = __ldg(reinterpret_cast<const int4*>(ei + base));
    int4 d = __ldg(reinterpret_cast<const int4*>(ei + N_EDGES + base));

    int p0 = atomicAdd(&g_count[d.x], 1);
    int p1 = atomicAdd(&g_count[d.y], 1);
    int p2 = atomicAdd(&g_count[d.z], 1);
    int p3 = atomicAdd(&g_count[d.w], 1);
    if (p0 < CAP) g_csr[p0 * N_NODES + d.x] = s.x;
    if (p1 < CAP) g_csr[p1 * N_NODES + d.y] = s.y;
    if (p2 < CAP) g_csr[p2 * N_NODES + d.z] = s.z;
    if (p3 < CAP) g_csr[p3 * N_NODES + d.w] = s.w;
}

// shared pull helper: fp32 accumulate of fp16 neighbor rows, 4-deep software pipeline
__device__ __forceinline__ void pull_rows(const __half* __restrict__ feat,
                                          int node, int deg, float* acc) {
    const uint4* rows = reinterpret_cast<const uint4*>(feat);
    int e = 0;
    for (; e + 4 <= deg; e += 4) {
        int s0 = __ldg(&g_csr[(e + 0) * N_NODES + node]);
        int s1 = __ldg(&g_csr[(e + 1) * N_NODES + node]);
        int s2 = __ldg(&g_csr[(e + 2) * N_NODES + node]);
        int s3 = __ldg(&g_csr[(e + 3) * N_NODES + node]);
        uint4 r0 = __ldg(rows + s0);
        uint4 r1 = __ldg(rows + s1);
        uint4 r2 = __ldg(rows + s2);
        uint4 r3 = __ldg(rows + s3);
        acc_half8(acc, r0); acc_half8(acc, r1);
        acc_half8(acc, r2); acc_half8(acc, r3);
    }
    for (; e < deg; e++) {
        int s = __ldg(&g_csr[e * N_NODES + node]);
        acc_half8(acc, __ldg(rows + s));
    }
}

// ---------------- K3: pull layer 1 + relu (thread per node) ----------------
__global__ __launch_bounds__(128)
void k_pull1() {
    int i = blockIdx.x * blockDim.x + threadIdx.x;
    if (i >= N_NODES) return;
    int deg = min(g_count[i], CAP);

    float a[R1] = {0.f, 0.f, 0.f, 0.f, 0.f, 0.f, 0.f, 0.f};
    pull_rows(g_y1h, i, deg, a);

    const float4* rp = reinterpret_cast<const float4*>(g_r1 + (size_t)i * R1);
    float4 r0 = rp[0], r1v = rp[1];
    float h[R1];
    h[0] = fmaxf(a[0] + r0.x, 0.f);  h[1] = fmaxf(a[1] + r0.y, 0.f);
    h[2] = fmaxf(a[2] + r0.z, 0.f);  h[3] = fmaxf(a[3] + r0.w, 0.f);
    h[4] = fmaxf(a[4] + r1v.x, 0.f); h[5] = fmaxf(a[5] + r1v.y, 0.f);
    h[6] = fmaxf(a[6] + r1v.z, 0.f); h[7] = fmaxf(a[7] + r1v.w, 0.f);

    reinterpret_cast<uint4*>(g_h1h)[i] = pack_half8(h);
    float4* hf = reinterpret_cast<float4*>(g_h1f + (size_t)i * R1);
    hf[0] = make_float4(h[0], h[1], h[2], h[3]);
    hf[1] = make_float4(h[4], h[5], h[6], h[7]);
}

// ---------------- K4: pull layer 2 + conv2 + fc1 + fc2 + sum (thread per node) ----------------
__global__ __launch_bounds__(128)
void k_pull2(const float* __restrict__ Wrel2,
             const float* __restrict__ brel2,
             const float* __restrict__ Wroot2,
             const float* __restrict__ Wfc1,
             const float* __restrict__ bfc1,
             const float* __restrict__ Wfc2,
             const float* __restrict__ bfc2,
             float* __restrict__ out) {
    __shared__ float sWr[R1 * R2];
    __shared__ float sWo[R1 * R2];
    __shared__ float sb2[R2];
    __shared__ float sF1[R2 * N1];
    __shared__ float sb3[N1];
    __shared__ float sF2[N1];
    __shared__ float sbf2;
    __shared__ float sred[128 / 32];

    int t = threadIdx.x;
    for (int j = t; j < R1 * R2; j += blockDim.x) { sWr[j] = Wrel2[j]; sWo[j] = Wroot2[j]; }
    for (int j = t; j < R2 * N1; j += blockDim.x) sF1[j] = Wfc1[j];
    if (t < R2) sb2[t] = brel2[t];
    if (t < N1) { sb3[t] = bfc1[t]; sF2[t] = Wfc2[t]; }
    if (t == 0) sbf2 = bfc2[0];
    __syncthreads();

    int i = blockIdx.x * blockDim.x + t;
    float o = 0.f;
    if (i < N_NODES) {
        int deg = min(g_count[i], CAP);
        float a[R1] = {0.f, 0.f, 0.f, 0.f, 0.f, 0.f, 0.f, 0.f};
        pull_rows(g_h1h, i, deg, a);

        const float4* hp = reinterpret_cast<const float4*>(g_h1f + (size_t)i * R1);
        float4 u = hp[0], v = hp[1];
        float hr[R1] = {u.x, u.y, u.z, u.w, v.x, v.y, v.z, v.w};

        float h2[R2];
#pragma unroll
        for (int k = 0; k < R2; k++) h2[k] = sb2[k];
#pragma unroll
        for (int j = 0; j < R1; j++) {
            float aj = a[j], hj = hr[j];
#pragma unroll
            for (int k = 0; k < R2; k++)
                h2[k] += aj * sWr[j * R2 + k] + hj * sWo[j * R2 + k];
        }
#pragma unroll
        for (int k = 0; k < R2; k++) h2[k] = fmaxf(h2[k], 0.f);

        o = sbf2;
#pragma unroll
        for (int m = 0; m < N1; m++) {
            float acc = sb3[m];
#pragma unroll
            for (int k = 0; k < R2; k++) acc += h2[k] * sF1[k * N1 + m];
            o += fmaxf(acc, 0.f) * sF2[m];
        }
        out[i] = o;
    }

    // block-level sum -> one double atomic per block
    float w = o;
#pragma unroll
    for (int off = 16; off > 0; off >>= 1)
        w += __shfl_down_sync(0xffffffffu, w, off);
    if ((t & 31) == 0) sred[t >> 5] = w;
    __syncthreads();
    if (t == 0) {
        float bs = sred[0] + sred[1] + sred[2] + sred[3];
        atomicAdd(&g_sum, (double)bs);
    }
}

// ---------------- K5: subtract mean ----------------
__global__ void k_mean(float* __restrict__ out) {
    int i = blockIdx.x * blockDim.x + threadIdx.x;
    if (i >= N_NODES) return;
    float m = (float)(g_sum / (double)N_NODES);
    out[i] -= m;
}

// ---------------- launch ----------------
extern "C" void kernel_launch(void* const* d_in, const int* in_sizes, int n_in,
                              void* d_out, int out_size) {
    const float* x      = (const float*)d_in[0];
    const int*   ei     = (const int*)d_in[1];
    const float* Wrel1  = (const float*)d_in[2];
    const float* brel1  = (const float*)d_in[3];
    const float* Wroot1 = (const float*)d_in[4];
    const float* Wrel2  = (const float*)d_in[5];
    const float* brel2  = (const float*)d_in[6];
    const float* Wroot2 = (const float*)d_in[7];
    const float* Wfc1   = (const float*)d_in[8];
    const float* bfc1   = (const float*)d_in[9];
    const float* Wfc2   = (const float*)d_in[10];
    const float* bfc2   = (const float*)d_in[11];
    float* out = (float*)d_out;

    const int node_blocks = (N_NODES + 127) / 128;      // 782
    const int scatter_blocks = N_EDGES / 4 / 256;       // 3125

    k_node1<<<node_blocks, 128>>>(x, Wrel1, brel1, Wroot1);
    k_scatter<<<scatter_blocks, 256>>>(ei);
    k_pull1<<<node_blocks, 128>>>();
    k_pull2<<<node_blocks, 128>>>(Wrel2, brel2, Wroot2, Wfc1, bfc1, Wfc2, bfc2, out);
    k_mean<<<node_blocks, 128>>>(out);
}

// round 6
// speedup vs baseline: 1.6295x; 1.0132x over previous
#include <cuda_runtime.h>
#include <cuda_fp16.h>

#define N_NODES 100000
#define N_EDGES 3200000
#define R0 16
#define R1 8
#define R2 16
#define N1 32
#define CAP 96   // max in-degree; Binomial(3.2M, 1e-5): mean 32, max ~60. 96 = 11 sigma.

// ---------------- scratch (device globals; no allocation allowed) ----------------
__device__ __align__(16) __half g_y1h[N_NODES * R1];  // x @ W_rel1, fp16 rows (gathered)
__device__ __align__(16) float  g_r1[N_NODES * R1];   // x @ W_root1 + b_rel1 (exact)
__device__ __align__(16) __half g_h1h[N_NODES * R1];  // layer-1 out, fp16 rows (gathered)
__device__ __align__(16) float  g_h1f[N_NODES * R1];  // layer-1 out, fp32 (root path)
__device__ __align__(16) float  g_agg2[N_NODES * R1]; // layer-2 aggregate (fp32)
__device__ int g_count[N_NODES];
__device__ int g_csr[CAP * N_NODES];                  // slot-major: csr[slot*N + node]
__device__ double g_sum;

// pack 8 floats -> 8 halves (16B)
__device__ __forceinline__ uint4 pack_half8(const float* v) {
    __half2 h0 = __float22half2_rn(make_float2(v[0], v[1]));
    __half2 h1 = __float22half2_rn(make_float2(v[2], v[3]));
    __half2 h2 = __float22half2_rn(make_float2(v[4], v[5]));
    __half2 h3 = __float22half2_rn(make_float2(v[6], v[7]));
    uint4 u;
    u.x = *reinterpret_cast<unsigned*>(&h0);
    u.y = *reinterpret_cast<unsigned*>(&h1);
    u.z = *reinterpret_cast<unsigned*>(&h2);
    u.w = *reinterpret_cast<unsigned*>(&h3);
    return u;
}

// accumulate a packed half8 row into fp32 acc[8]
__device__ __forceinline__ void acc_half8(float* acc, uint4 u) {
    __half2 h0 = *reinterpret_cast<__half2*>(&u.x);
    __half2 h1 = *reinterpret_cast<__half2*>(&u.y);
    __half2 h2 = *reinterpret_cast<__half2*>(&u.z);
    __half2 h3 = *reinterpret_cast<__half2*>(&u.w);
    float2 f0 = __half22float2(h0), f1 = __half22float2(h1);
    float2 f2 = __half22float2(h2), f3 = __half22float2(h3);
    acc[0] += f0.x; acc[1] += f0.y; acc[2] += f1.x; acc[3] += f1.y;
    acc[4] += f2.x; acc[5] += f2.y; acc[6] += f3.x; acc[7] += f3.y;
}

// ---------------- K1: per-node pre-transform + zero counters ----------------
__global__ __launch_bounds__(128)
void k_node1(const float* __restrict__ x,
             const float* __restrict__ Wrel,
             const float* __restrict__ brel,
             const float* __restrict__ Wroot) {
    __shared__ float sWr[R0 * R1];
    __shared__ float sWo[R0 * R1];
    __shared__ float sb[R1];
    int t = threadIdx.x;
    if (t < R0 * R1) { sWr[t] = Wrel[t]; sWo[t] = Wroot[t]; }
    if (t < R1) sb[t] = brel[t];
    __syncthreads();

    int i = blockIdx.x * blockDim.x + t;
    if (i == 0) g_sum = 0.0;
    if (i >= N_NODES) return;

    g_count[i] = 0;

    float xr[R0];
    const float4* xp = reinterpret_cast<const float4*>(x + (size_t)i * R0);
#pragma unroll
    for (int q = 0; q < R0 / 4; q++) {
        float4 v = xp[q];
        xr[4 * q + 0] = v.x; xr[4 * q + 1] = v.y;
        xr[4 * q + 2] = v.z; xr[4 * q + 3] = v.w;
    }

    float y[R1], r[R1];
#pragma unroll
    for (int k = 0; k < R1; k++) { y[k] = 0.f; r[k] = sb[k]; }
#pragma unroll
    for (int j = 0; j < R0; j++) {
        float xj = xr[j];
#pragma unroll
        for (int k = 0; k < R1; k++) {
            y[k] += xj * sWr[j * R1 + k];
            r[k] += xj * sWo[j * R1 + k];
        }
    }

    reinterpret_cast<uint4*>(g_y1h)[i] = pack_half8(y);
    float4* rp = reinterpret_cast<float4*>(g_r1 + (size_t)i * R1);
    rp[0] = make_float4(r[0], r[1], r[2], r[3]);
    rp[1] = make_float4(r[4], r[5], r[6], r[7]);
}

// ---------------- K2: build slot-major incoming CSR ----------------
__global__ __launch_bounds__(256)
void k_scatter(const int* __restrict__ ei) {
    int base = (blockIdx.x * blockDim.x + threadIdx.x) * 4;
    if (base >= N_EDGES) return;
    int4 s = __ldg(reinterpret_cast<const int4*>(ei + base));
    int4 d = __ldg(reinterpret_cast<const int4*>(ei + N_EDGES + base));

    int p0 = atomicAdd(&g_count[d.x], 1);
    int p1 = atomicAdd(&g_count[d.y], 1);
    int p2 = atomicAdd(&g_count[d.z], 1);
    int p3 = atomicAdd(&g_count[d.w], 1);
    if (p0 < CAP) g_csr[p0 * N_NODES + d.x] = s.x;
    if (p1 < CAP) g_csr[p1 * N_NODES + d.y] = s.y;
    if (p2 < CAP) g_csr[p2 * N_NODES + d.z] = s.z;
    if (p3 < CAP) g_csr[p3 * N_NODES + d.w] = s.w;
}

// ---------------- K3/K4: pull aggregate, 4 threads per node ----------------
// lane l of a node's group handles slots l, l+4, l+8, ... (pipelined x2)
// then 2 shfl_xor rounds combine the 4 partial sums.
template <int LAYER>
__global__ __launch_bounds__(256)
void k_pull4() {
    int t = threadIdx.x;
    int lane = t & 3;
    int node = blockIdx.x * 64 + (t >> 2);
    if (node >= N_NODES) return;

    const uint4* rows = reinterpret_cast<const uint4*>(LAYER == 1 ? g_y1h : g_h1h);
    int deg = min(__ldg(&g_count[node]), CAP);

    float a[R1] = {0.f, 0.f, 0.f, 0.f, 0.f, 0.f, 0.f, 0.f};
    int e = lane;
    // 2 slots in flight per thread -> 8 gathers in flight per node
    while (e + 4 < deg) {
        int s0 = __ldg(&g_csr[e * N_NODES + node]);
        int s1 = __ldg(&g_csr[(e + 4) * N_NODES + node]);
        uint4 r0 = __ldg(rows + s0);
        uint4 r1 = __ldg(rows + s1);
        acc_half8(a, r0);
        acc_half8(a, r1);
        e += 8;
    }
    if (e < deg) {
        int s = __ldg(&g_csr[e * N_NODES + node]);
        acc_half8(a, __ldg(rows + s));
    }

    // combine the 4 lanes' partials
#pragma unroll
    for (int k = 0; k < R1; k++) a[k] += __shfl_xor_sync(0xffffffffu, a[k], 1);
#pragma unroll
    for (int k = 0; k < R1; k++) a[k] += __shfl_xor_sync(0xffffffffu, a[k], 2);

    if (lane == 0) {
        if (LAYER == 1) {
            const float4* rp = reinterpret_cast<const float4*>(g_r1 + (size_t)node * R1);
            float4 r0 = rp[0], r1v = rp[1];
            float h[R1];
            h[0] = fmaxf(a[0] + r0.x, 0.f);  h[1] = fmaxf(a[1] + r0.y, 0.f);
            h[2] = fmaxf(a[2] + r0.z, 0.f);  h[3] = fmaxf(a[3] + r0.w, 0.f);
            h[4] = fmaxf(a[4] + r1v.x, 0.f); h[5] = fmaxf(a[5] + r1v.y, 0.f);
            h[6] = fmaxf(a[6] + r1v.z, 0.f); h[7] = fmaxf(a[7] + r1v.w, 0.f);
            reinterpret_cast<uint4*>(g_h1h)[node] = pack_half8(h);
            float4* hf = reinterpret_cast<float4*>(g_h1f + (size_t)node * R1);
            hf[0] = make_float4(h[0], h[1], h[2], h[3]);
            hf[1] = make_float4(h[4], h[5], h[6], h[7]);
        } else {
            float4* ap = reinterpret_cast<float4*>(g_agg2 + (size_t)node * R1);
            ap[0] = make_float4(a[0], a[1], a[2], a[3]);
            ap[1] = make_float4(a[4], a[5], a[6], a[7]);
        }
    }
}

// ---------------- K5: conv2 + fc1 + fc2 + sum (thread per node) ----------------
__global__ __launch_bounds__(128)
void k_node2(const float* __restrict__ Wrel2,
             const float* __restrict__ brel2,
             const float* __restrict__ Wroot2,
             const float* __restrict__ Wfc1,
             const float* __restrict__ bfc1,
             const float* __restrict__ Wfc2,
             const float* __restrict__ bfc2,
             float* __restrict__ out) {
    __shared__ float sWr[R1 * R2];
    __shared__ float sWo[R1 * R2];
    __shared__ float sb2[R2];
    __shared__ float sF1[R2 * N1];
    __shared__ float sb3[N1];
    __shared__ float sF2[N1];
    __shared__ float sbf2;
    __shared__ float sred[4];

    int t = threadIdx.x;
    for (int j = t; j < R1 * R2; j += blockDim.x) { sWr[j] = Wrel2[j]; sWo[j] = Wroot2[j]; }
    for (int j = t; j < R2 * N1; j += blockDim.x) sF1[j] = Wfc1[j];
    if (t < R2) sb2[t] = brel2[t];
    if (t < N1) { sb3[t] = bfc1[t]; sF2[t] = Wfc2[t]; }
    if (t == 0) sbf2 = bfc2[0];
    __syncthreads();

    int i = blockIdx.x * blockDim.x + t;
    float o = 0.f;
    if (i < N_NODES) {
        const float4* ap = reinterpret_cast<const float4*>(g_agg2 + (size_t)i * R1);
        const float4* hp = reinterpret_cast<const float4*>(g_h1f + (size_t)i * R1);
        float4 u = ap[0], v = ap[1];
        float a[R1] = {u.x, u.y, u.z, u.w, v.x, v.y, v.z, v.w};
        u = hp[0]; v = hp[1];
        float hr[R1] = {u.x, u.y, u.z, u.w, v.x, v.y, v.z, v.w};

        float h2[R2];
#pragma unroll
        for (int k = 0; k < R2; k++) h2[k] = sb2[k];
#pragma unroll
        for (int j = 0; j < R1; j++) {
            float aj = a[j], hj = hr[j];
#pragma unroll
            for (int k = 0; k < R2; k++)
                h2[k] += aj * sWr[j * R2 + k] + hj * sWo[j * R2 + k];
        }
#pragma unroll
        for (int k = 0; k < R2; k++) h2[k] = fmaxf(h2[k], 0.f);

        o = sbf2;
#pragma unroll
        for (int m = 0; m < N1; m++) {
            float acc = sb3[m];
#pragma unroll
            for (int k = 0; k < R2; k++) acc += h2[k] * sF1[k * N1 + m];
            o += fmaxf(acc, 0.f) * sF2[m];
        }
        out[i] = o;
    }

    // block-level sum -> one double atomic per block
    float w = o;
#pragma unroll
    for (int off = 16; off > 0; off >>= 1)
        w += __shfl_down_sync(0xffffffffu, w, off);
    if ((t & 31) == 0) sred[t >> 5] = w;
    __syncthreads();
    if (t == 0) {
        float bs = sred[0] + sred[1] + sred[2] + sred[3];
        atomicAdd(&g_sum, (double)bs);
    }
}

// ---------------- K6: subtract mean ----------------
__global__ void k_mean(float* __restrict__ out) {
    int i = blockIdx.x * blockDim.x + threadIdx.x;
    if (i >= N_NODES) return;
    float m = (float)(g_sum / (double)N_NODES);
    out[i] -= m;
}

// ---------------- launch ----------------
extern "C" void kernel_launch(void* const* d_in, const int* in_sizes, int n_in,
                              void* d_out, int out_size) {
    const float* x      = (const float*)d_in[0];
    const int*   ei     = (const int*)d_in[1];
    const float* Wrel1  = (const float*)d_in[2];
    const float* brel1  = (const float*)d_in[3];
    const float* Wroot1 = (const float*)d_in[4];
    const float* Wrel2  = (const float*)d_in[5];
    const float* brel2  = (const float*)d_in[6];
    const float* Wroot2 = (const float*)d_in[7];
    const float* Wfc1   = (const float*)d_in[8];
    const float* bfc1   = (const float*)d_in[9];
    const float* Wfc2   = (const float*)d_in[10];
    const float* bfc2   = (const float*)d_in[11];
    float* out = (float*)d_out;

    const int node_blocks = (N_NODES + 127) / 128;      // 782
    const int scatter_blocks = N_EDGES / 4 / 256;       // 3125
    const int pull_blocks = (N_NODES + 63) / 64;        // 1563

    k_node1<<<node_blocks, 128>>>(x, Wrel1, brel1, Wroot1);
    k_scatter<<<scatter_blocks, 256>>>(ei);
    k_pull4<1><<<pull_blocks, 256>>>();
    k_pull4<2><<<pull_blocks, 256>>>();
    k_node2<<<node_blocks, 128>>>(Wrel2, brel2, Wroot2, Wfc1, bfc1, Wfc2, bfc2, out);
    k_mean<<<node_blocks, 128>>>(out);
}